// round 1
// baseline (speedup 1.0000x reference)
#include <cuda_runtime.h>
#include <cuda_bf16.h>

// CoralLossV2: mean over (B, Km1) of BCE-with-logits(logits, levels)
// where levels[i,k] = (targets[i] > k).
// loss = max(x,0) - x*z + log1p(exp(-|x|))
//
// Strategy: HBM-bound streaming reduction.
//  - kernel 1: grid-stride over float4-packed logits (coalesced), per-thread
//    fp32 accumulate, block reduce, write per-block partial to __device__ scratch.
//  - kernel 2: single block deterministically reduces partials, scales by 1/N.

#define NBLOCKS 2048
#define NTHREADS 256

__device__ float g_partials[NBLOCKS];

__device__ __forceinline__ float bce_elem(float x, float z) {
    // max(x,0) - x*z + log(1 + exp(-|x|))
    float a = fabsf(x);
    float t = __logf(1.0f + __expf(-a));
    return fmaxf(x, 0.0f) - x * z + t;
}

__global__ __launch_bounds__(NTHREADS)
void coral_partial_kernel(const float4* __restrict__ logits4,
                          const long long* __restrict__ targets,
                          int nvec /* = B*16 */) {
    int tid = blockIdx.x * blockDim.x + threadIdx.x;
    int stride = gridDim.x * blockDim.x;

    float acc = 0.0f;
    for (int i = tid; i < nvec; i += stride) {
        float4 v = logits4[i];
        long long t = targets[i >> 4];       // 16 float4 per row of 64
        int kbase = (i & 15) << 2;           // first threshold index in this vec4
        float z0 = (t > (long long)(kbase + 0)) ? 1.0f : 0.0f;
        float z1 = (t > (long long)(kbase + 1)) ? 1.0f : 0.0f;
        float z2 = (t > (long long)(kbase + 2)) ? 1.0f : 0.0f;
        float z3 = (t > (long long)(kbase + 3)) ? 1.0f : 0.0f;
        acc += bce_elem(v.x, z0);
        acc += bce_elem(v.y, z1);
        acc += bce_elem(v.z, z2);
        acc += bce_elem(v.w, z3);
    }

    // warp reduce
    #pragma unroll
    for (int off = 16; off > 0; off >>= 1)
        acc += __shfl_xor_sync(0xFFFFFFFF, acc, off);

    __shared__ float warp_sums[NTHREADS / 32];
    int lane = threadIdx.x & 31;
    int wid  = threadIdx.x >> 5;
    if (lane == 0) warp_sums[wid] = acc;
    __syncthreads();

    if (wid == 0) {
        float s = (lane < NTHREADS / 32) ? warp_sums[lane] : 0.0f;
        #pragma unroll
        for (int off = 4; off > 0; off >>= 1)
            s += __shfl_xor_sync(0xFFFFFFFF, s, off);
        if (lane == 0) g_partials[blockIdx.x] = s;
    }
}

__global__ __launch_bounds__(NTHREADS)
void coral_final_kernel(float* __restrict__ out, float inv_n) {
    float acc = 0.0f;
    for (int i = threadIdx.x; i < NBLOCKS; i += NTHREADS)
        acc += g_partials[i];

    #pragma unroll
    for (int off = 16; off > 0; off >>= 1)
        acc += __shfl_xor_sync(0xFFFFFFFF, acc, off);

    __shared__ float warp_sums[NTHREADS / 32];
    int lane = threadIdx.x & 31;
    int wid  = threadIdx.x >> 5;
    if (lane == 0) warp_sums[wid] = acc;
    __syncthreads();

    if (wid == 0) {
        float s = (lane < NTHREADS / 32) ? warp_sums[lane] : 0.0f;
        #pragma unroll
        for (int off = 4; off > 0; off >>= 1)
            s += __shfl_xor_sync(0xFFFFFFFF, s, off);
        if (lane == 0) out[0] = s * inv_n;
    }
}

extern "C" void kernel_launch(void* const* d_in, const int* in_sizes, int n_in,
                              void* d_out, int out_size) {
    const float4*    logits4 = (const float4*)d_in[0];
    const long long* targets = (const long long*)d_in[1];
    float*           out     = (float*)d_out;

    long long n_elem = (long long)in_sizes[0];   // B * 64
    int nvec = (int)(n_elem >> 2);               // float4 count
    float inv_n = 1.0f / (float)n_elem;

    coral_partial_kernel<<<NBLOCKS, NTHREADS>>>(logits4, targets, nvec);
    coral_final_kernel<<<1, NTHREADS>>>(out, inv_n);
}

// round 3
// speedup vs baseline: 1.1919x; 1.1919x over previous
#include <cuda_runtime.h>
#include <cuda_bf16.h>

// CoralLossV2: mean over (B, Km1=64) of BCE-with-logits(logits, levels),
// levels[i,k] = (targets[i] > k).
// loss = max(x,0) - x*z + log1p(exp(-|x|))
//
// Single-kernel HBM-bound streaming reduction:
//  - grid-stride over float4-packed logits, 4-way batched loads for MLP
//  - block reduce -> per-block partial in __device__ scratch
//  - last block (atomic counter) deterministically reduces all partials

#define NBLOCKS 2048
#define NTHREADS 256

__device__ float g_partials[NBLOCKS];
__device__ unsigned int g_counter = 0;   // self-resetting each launch

__device__ __forceinline__ float bce_elem(float x, float z) {
    float a = fabsf(x);
    float t = __logf(1.0f + __expf(-a));
    return fmaxf(x, 0.0f) - x * z + t;
}

__device__ __forceinline__ float bce_vec4(float4 v, int t, int kbase) {
    float z0 = (t > kbase + 0) ? 1.0f : 0.0f;
    float z1 = (t > kbase + 1) ? 1.0f : 0.0f;
    float z2 = (t > kbase + 2) ? 1.0f : 0.0f;
    float z3 = (t > kbase + 3) ? 1.0f : 0.0f;
    return bce_elem(v.x, z0) + bce_elem(v.y, z1) +
           bce_elem(v.z, z2) + bce_elem(v.w, z3);
}

__device__ __forceinline__ float block_reduce(float acc, float* warp_sums) {
    #pragma unroll
    for (int off = 16; off > 0; off >>= 1)
        acc += __shfl_xor_sync(0xFFFFFFFF, acc, off);
    int lane = threadIdx.x & 31;
    int wid  = threadIdx.x >> 5;
    if (lane == 0) warp_sums[wid] = acc;
    __syncthreads();
    float s = 0.0f;
    if (wid == 0) {
        s = (lane < NTHREADS / 32) ? warp_sums[lane] : 0.0f;
        #pragma unroll
        for (int off = 4; off > 0; off >>= 1)
            s += __shfl_xor_sync(0xFFFFFFFF, s, off);
    }
    return s;  // valid in warp 0 lane 0
}

__global__ __launch_bounds__(NTHREADS)
void coral_fused_kernel(const float4* __restrict__ logits4,
                        const int* __restrict__ targets32, // low words of int64
                        int nvec, float inv_n,
                        float* __restrict__ out) {
    const int tid    = blockIdx.x * blockDim.x + threadIdx.x;
    const int stride = gridDim.x * blockDim.x;

    float acc = 0.0f;

    // 4-way batched main loop: 4 independent LDG.128 + 4 LDG.32 in flight.
    int i = tid;
    for (; i + 3 * stride < nvec; i += 4 * stride) {
        int i0 = i, i1 = i + stride, i2 = i + 2 * stride, i3 = i + 3 * stride;
        float4 v0 = logits4[i0];
        float4 v1 = logits4[i1];
        float4 v2 = logits4[i2];
        float4 v3 = logits4[i3];
        int t0 = targets32[(i0 >> 4) * 2];
        int t1 = targets32[(i1 >> 4) * 2];
        int t2 = targets32[(i2 >> 4) * 2];
        int t3 = targets32[(i3 >> 4) * 2];
        acc += bce_vec4(v0, t0, (i0 & 15) << 2);
        acc += bce_vec4(v1, t1, (i1 & 15) << 2);
        acc += bce_vec4(v2, t2, (i2 & 15) << 2);
        acc += bce_vec4(v3, t3, (i3 & 15) << 2);
    }
    for (; i < nvec; i += stride) {
        float4 v = logits4[i];
        int t = targets32[(i >> 4) * 2];
        acc += bce_vec4(v, t, (i & 15) << 2);
    }

    __shared__ float warp_sums[NTHREADS / 32];
    float bsum = block_reduce(acc, warp_sums);

    __shared__ bool is_last;
    if (threadIdx.x == 0) {
        g_partials[blockIdx.x] = bsum;
        __threadfence();
        unsigned int done = atomicAdd(&g_counter, 1u);
        is_last = (done == (unsigned int)(gridDim.x - 1));
    }
    __syncthreads();

    if (is_last) {
        // Deterministic final reduction: fixed order per thread, fixed tree.
        float facc = 0.0f;
        #pragma unroll
        for (int j = threadIdx.x; j < NBLOCKS; j += NTHREADS)
            facc += g_partials[j];
        __syncthreads();  // reuse of warp_sums
        float fsum = block_reduce(facc, warp_sums);
        if (threadIdx.x == 0) {
            out[0] = fsum * inv_n;
            g_counter = 0;  // reset for next launch / graph replay
        }
    }
}

extern "C" void kernel_launch(void* const* d_in, const int* in_sizes, int n_in,
                              void* d_out, int out_size) {
    const float4* logits4   = (const float4*)d_in[0];
    const int*    targets32 = (const int*)d_in[1];  // int64 low words (targets >= 0)
    float*        out       = (float*)d_out;

    long long n_elem = (long long)in_sizes[0];  // B * 64 = 2^25
    int nvec = (int)(n_elem >> 2);
    float inv_n = 1.0f / (float)n_elem;

    coral_fused_kernel<<<NBLOCKS, NTHREADS>>>(logits4, targets32, nvec, inv_n, out);
}

// round 4
// speedup vs baseline: 1.2773x; 1.0717x over previous
#include <cuda_runtime.h>
#include <cuda_bf16.h>

// CoralLossV2: mean over (B, Km1=64) of BCE-with-logits(logits, levels),
// levels[i,k] = (targets[i] > k).
// loss = max(x,0) - x*z + log1p(exp(-|x|))
//
// Single fused kernel. Fast path exploits the fixed shape (nvec = 2^23 =
// 16 * NBLOCKS * NTHREADS): compile-time trip count, loop-invariant kbase
// (stride is a multiple of 16), constant-stride target pointer. Accumulates
// log2(1+e) (scale by ln2 once), relu-sum, and predicated z-sum separately.

#define NBLOCKS  2048
#define NTHREADS 256
#define NITER    16                      // vec4 per thread on the fast path
#define STRIDE   (NBLOCKS * NTHREADS)    // 524288, multiple of 16
#define TSTEP    ((STRIDE >> 4) * 2)     // int32 stride into int64 targets

__device__ float g_partials[NBLOCKS];
__device__ unsigned int g_counter = 0;   // self-resetting each launch

__device__ __forceinline__ float block_reduce(float acc, float* warp_sums) {
    #pragma unroll
    for (int off = 16; off > 0; off >>= 1)
        acc += __shfl_xor_sync(0xFFFFFFFF, acc, off);
    int lane = threadIdx.x & 31;
    int wid  = threadIdx.x >> 5;
    if (lane == 0) warp_sums[wid] = acc;
    __syncthreads();
    float s = 0.0f;
    if (wid == 0) {
        s = (lane < NTHREADS / 32) ? warp_sums[lane] : 0.0f;
        #pragma unroll
        for (int off = 4; off > 0; off >>= 1)
            s += __shfl_xor_sync(0xFFFFFFFF, s, off);
    }
    return s;  // valid in warp 0 lane 0
}

__device__ __forceinline__ void finish(float bsum, float inv_n,
                                       float* __restrict__ out,
                                       float* warp_sums) {
    __shared__ bool is_last;
    if (threadIdx.x == 0) {
        g_partials[blockIdx.x] = bsum;
        __threadfence();
        unsigned int done = atomicAdd(&g_counter, 1u);
        is_last = (done == (unsigned int)(gridDim.x - 1));
    }
    __syncthreads();
    if (is_last) {
        float facc = 0.0f;
        for (int j = threadIdx.x; j < (int)gridDim.x; j += NTHREADS)
            facc += g_partials[j];
        __syncthreads();
        float fsum = block_reduce(facc, warp_sums);
        if (threadIdx.x == 0) {
            out[0] = fsum * inv_n;
            g_counter = 0;
        }
    }
}

// per-element: acc2 += log2(1+exp(-|x|)); accr += relu(x); if(z) accz += x
__device__ __forceinline__ void proc1(float x, bool z,
                                      float& acc2, float& accr, float& accz) {
    float e = __expf(-fabsf(x));     // FMUL(|x|*-log2e) + MUFU.EX2
    acc2 += __log2f(1.0f + e);       // FADD + MUFU.LG2 + FADD
    accr += fmaxf(x, 0.0f);          // FMAX + FADD
    if (z) accz += x;                // ISETP + predicated FADD
}

__device__ __forceinline__ void proc4(float4 v, int c /* t - kbase */,
                                      float& acc2, float& accr, float& accz) {
    proc1(v.x, c > 0, acc2, accr, accz);
    proc1(v.y, c > 1, acc2, accr, accz);
    proc1(v.z, c > 2, acc2, accr, accz);
    proc1(v.w, c > 3, acc2, accr, accz);
}

__global__ __launch_bounds__(NTHREADS)
void coral_fast_kernel(const float4* __restrict__ logits4,
                       const int* __restrict__ targets32,
                       float inv_n, float* __restrict__ out) {
    const int tid = blockIdx.x * NTHREADS + threadIdx.x;
    const int kb  = (tid & 15) << 2;            // loop-invariant
    const float4* p  = logits4 + tid;
    const int*    tp = targets32 + ((tid >> 4) << 1);

    float acc2 = 0.0f, accr = 0.0f, accz = 0.0f;

    #pragma unroll
    for (int mm = 0; mm < NITER / 4; mm++) {
        float4 v0 = __ldcs(p + (size_t)(mm * 4 + 0) * STRIDE);
        float4 v1 = __ldcs(p + (size_t)(mm * 4 + 1) * STRIDE);
        float4 v2 = __ldcs(p + (size_t)(mm * 4 + 2) * STRIDE);
        float4 v3 = __ldcs(p + (size_t)(mm * 4 + 3) * STRIDE);
        int t0 = __ldg(tp + (mm * 4 + 0) * TSTEP);
        int t1 = __ldg(tp + (mm * 4 + 1) * TSTEP);
        int t2 = __ldg(tp + (mm * 4 + 2) * TSTEP);
        int t3 = __ldg(tp + (mm * 4 + 3) * TSTEP);
        proc4(v0, t0 - kb, acc2, accr, accz);
        proc4(v1, t1 - kb, acc2, accr, accz);
        proc4(v2, t2 - kb, acc2, accr, accz);
        proc4(v3, t3 - kb, acc2, accr, accz);
    }

    float acc = accr + 0.693147180559945f * acc2 - accz;

    __shared__ float warp_sums[NTHREADS / 32];
    float bsum = block_reduce(acc, warp_sums);
    finish(bsum, inv_n, out, warp_sums);
}

// Generic fallback (any shape with Km1 = 64, nvec arbitrary)
__global__ __launch_bounds__(NTHREADS)
void coral_generic_kernel(const float4* __restrict__ logits4,
                          const int* __restrict__ targets32,
                          int nvec, float inv_n, float* __restrict__ out) {
    const int tid    = blockIdx.x * blockDim.x + threadIdx.x;
    const int stride = gridDim.x * blockDim.x;

    float acc2 = 0.0f, accr = 0.0f, accz = 0.0f;
    for (int i = tid; i < nvec; i += stride) {
        float4 v = logits4[i];
        int t = targets32[(i >> 4) * 2];
        proc4(v, t - ((i & 15) << 2), acc2, accr, accz);
    }
    float acc = accr + 0.693147180559945f * acc2 - accz;

    __shared__ float warp_sums[NTHREADS / 32];
    float bsum = block_reduce(acc, warp_sums);
    finish(bsum, inv_n, out, warp_sums);
}

extern "C" void kernel_launch(void* const* d_in, const int* in_sizes, int n_in,
                              void* d_out, int out_size) {
    const float4* logits4   = (const float4*)d_in[0];
    const int*    targets32 = (const int*)d_in[1];  // int64 low words (targets >= 0)
    float*        out       = (float*)d_out;

    long long n_elem = (long long)in_sizes[0];  // B * 64
    int nvec = (int)(n_elem >> 2);
    float inv_n = 1.0f / (float)n_elem;

    if (nvec == NITER * STRIDE) {
        coral_fast_kernel<<<NBLOCKS, NTHREADS>>>(logits4, targets32, inv_n, out);
    } else {
        coral_generic_kernel<<<NBLOCKS, NTHREADS>>>(logits4, targets32, nvec,
                                                    inv_n, out);
    }
}